// round 5
// baseline (speedup 1.0000x reference)
#include <cuda_runtime.h>

// ---------------------------------------------------------------------------
// DiverseRegDCConv2d: per-sample dynamically-generated 3x3 conv.
//   wgen[b,o,c,kh,kw] = sum_n se[b,n] * weight[(o*C+c)*9+kh*3+kw, n]
//   out[b,o,h,w] = sum_{c,kh,kw} wgen[b,o,c,kh,kw] * x[b,c,h+kh-1,w+kw-1] + bias[o]
// B=32, C=O=256, H=W=28, K=3, NUM=8.
// ---------------------------------------------------------------------------

#define BB   32
#define CIN  256
#define COUT 256
#define HH   28
#define WW   28
#define NUMK 8
#define WROW 2304            // CIN*9 floats per output channel
#define NWG  589824          // COUT*WROW

// Scratch for generated per-sample weights: 32 * 589824 floats = 75.5 MB
__device__ float g_wgen[(size_t)BB * NWG];

typedef unsigned long long ULL;

__device__ __forceinline__ ULL pack2(float lo, float hi) {
    ULL r; asm("mov.b64 %0, {%1, %2};" : "=l"(r) : "f"(lo), "f"(hi)); return r;
}
__device__ __forceinline__ ULL ffma2(ULL a, ULL b, ULL c) {
    ULL d; asm("fma.rn.f32x2 %0, %1, %2, %3;" : "=l"(d) : "l"(a), "l"(b), "l"(c)); return d;
}
__device__ __forceinline__ float2 unpack2(ULL v) {
    float2 f; asm("mov.b64 {%0, %1}, %2;" : "=f"(f.x), "=f"(f.y) : "l"(v)); return f;
}

// ---------------------------------------------------------------------------
// Stage 1: weight generation. Each thread owns one row j of the weight bank
// (8 floats, kept in registers) and produces wgen for all 32 samples, so the
// 18.9 MB bank is read from DRAM exactly once. Stores are fully coalesced.
// ---------------------------------------------------------------------------
__global__ void wgen_kernel(const float* __restrict__ wbank,
                            const float* __restrict__ se) {
    __shared__ float s_se[BB * NUMK];   // 256 floats
    int tid = threadIdx.x;
    s_se[tid] = se[tid];
    __syncthreads();

    unsigned j = blockIdx.x * 256u + tid;     // < 589824 (grid exact)
    const float4* w4 = (const float4*)wbank;
    float4 w0 = w4[2u * j];
    float4 w1 = w4[2u * j + 1u];

    #pragma unroll 4
    for (int b = 0; b < BB; ++b) {
        const float* s = &s_se[b * NUMK];
        float v = w0.x * s[0];
        v = fmaf(w0.y, s[1], v);
        v = fmaf(w0.z, s[2], v);
        v = fmaf(w0.w, s[3], v);
        v = fmaf(w1.x, s[4], v);
        v = fmaf(w1.y, s[5], v);
        v = fmaf(w1.z, s[6], v);
        v = fmaf(w1.w, s[7], v);
        g_wgen[(size_t)b * NWG + j] = v;
    }
}

// ---------------------------------------------------------------------------
// Stage 2: per-sample direct conv, fp32x2 packed-FMA inner loop.
// Block: 32 output channels x 14 output rows. blockDim = (16, 14) = 224 thr.
// Thread: 2 output channels (tx, tx+16) x one full 28-col row -> 14 f32x2 accs
// per channel. Channels processed in chunks of 8 through shared memory.
// ---------------------------------------------------------------------------
#define CC_CHUNK 8
#define O_TILE   32
#define ROW_TILE 14
#define WSTRIDE  73          // 72 weights padded to 73 -> conflict-free LDS

__global__ __launch_bounds__(224, 2)
void dconv_kernel(const float* __restrict__ x,
                  const float* __restrict__ bias,
                  float* __restrict__ out) {
    __shared__ float wsm[O_TILE * WSTRIDE];          // 32 x 73
    __shared__ float xsm[CC_CHUNK][ROW_TILE + 2][32];// 8 x 16 x 32

    const int tx  = threadIdx.x;          // 0..15 : o-lane
    const int ty  = threadIdx.y;          // 0..13 : row
    const int tid = tx + ty * 16;         // 0..223

    const int b       = blockIdx.y;
    const int ob      = blockIdx.x >> 1;  // 0..7
    const int rb      = blockIdx.x & 1;   // 0..1
    const int oBase   = ob * O_TILE;
    const int rowBase = rb * ROW_TILE;

    ULL acc[2][14];
    #pragma unroll
    for (int oo = 0; oo < 2; ++oo)
        #pragma unroll
        for (int j = 0; j < 14; ++j) acc[oo][j] = 0ull;

    const float* wg = g_wgen + ((size_t)b * COUT + oBase) * WROW; // [32][2304]
    const float* xb = x + (size_t)b * CIN * (HH * WW);

    for (int c0 = 0; c0 < CIN; c0 += CC_CHUNK) {
        __syncthreads();   // previous chunk's smem reads done before refill

        // --- fill weight tile: 32 o x 72 floats (coalesced ldg, conflict-free sts)
        for (int i = tid; i < O_TILE * 72; i += 224) {
            int o = i / 72;
            int r = i - o * 72;
            wsm[o * WSTRIDE + r] = wg[(size_t)o * WROW + c0 * 9 + r];
        }
        // --- fill input tile: 8cc x 16 rows x 32 cols, zero-padded halo
        for (int i = tid; i < CC_CHUNK * 16 * 32; i += 224) {
            int cc  = i >> 9;
            int rem = i & 511;
            int row = rem >> 5;
            int s   = rem & 31;
            int ih  = rowBase - 1 + row;
            int iw  = s - 1;
            float v = 0.0f;
            if ((unsigned)ih < (unsigned)HH && (unsigned)iw < (unsigned)WW)
                v = xb[((c0 + cc) * HH + ih) * WW + iw];
            ((float*)xsm)[i] = v;
        }
        __syncthreads();

        for (int cc = 0; cc < CC_CHUNK; ++cc) {
            #pragma unroll
            for (int r = 0; r < 3; ++r) {
                // weights for (cc, kh=r): 2 channels x 3 taps, packed (w,w)
                ULL w2[2][3];
                #pragma unroll
                for (int oo = 0; oo < 2; ++oo) {
                    const float* wp = &wsm[(tx + 16 * oo) * WSTRIDE + cc * 9 + r * 3];
                    #pragma unroll
                    for (int kc = 0; kc < 3; ++kc) {
                        float wv = wp[kc];
                        w2[oo][kc] = pack2(wv, wv);
                    }
                }
                const float2* Ep = (const float2*)&xsm[cc][ty + r][0];
                float2 e0  = Ep[0];
                ULL   aE0  = pack2(e0.x, e0.y);
                float e0y  = e0.y;
                #pragma unroll
                for (int j = 0; j < 14; ++j) {
                    float2 e1 = Ep[j + 1];
                    ULL aE1 = pack2(e1.x, e1.y);     // cols 2j+2, 2j+3
                    ULL aD  = pack2(e0y, e1.x);      // cols 2j+1, 2j+2
                    acc[0][j] = ffma2(w2[0][0], aE0, acc[0][j]);
                    acc[0][j] = ffma2(w2[0][1], aD,  acc[0][j]);
                    acc[0][j] = ffma2(w2[0][2], aE1, acc[0][j]);
                    acc[1][j] = ffma2(w2[1][0], aE0, acc[1][j]);
                    acc[1][j] = ffma2(w2[1][1], aD,  acc[1][j]);
                    acc[1][j] = ffma2(w2[1][2], aE1, acc[1][j]);
                    aE0 = aE1;
                    e0y = e1.y;
                }
            }
        }
    }

    // --- epilogue: add bias, store one full row per (thread, channel)
    const int h = rowBase + ty;
    #pragma unroll
    for (int oo = 0; oo < 2; ++oo) {
        int o = oBase + tx + 16 * oo;
        float bv = bias[o];
        float2* op = (float2*)(out + (((size_t)b * COUT + o) * HH + h) * WW);
        #pragma unroll
        for (int j = 0; j < 14; ++j) {
            float2 v = unpack2(acc[oo][j]);
            v.x += bv;
            v.y += bv;
            op[j] = v;
        }
    }
}

// ---------------------------------------------------------------------------
// Harness entry. Inputs (metadata order): inputs, inputs_se, weight, bias.
// ---------------------------------------------------------------------------
extern "C" void kernel_launch(void* const* d_in, const int* in_sizes, int n_in,
                              void* d_out, int out_size) {
    const float* x    = (const float*)d_in[0];   // [32,256,28,28]
    const float* se   = (const float*)d_in[1];   // [32,8]
    const float* wbk  = (const float*)d_in[2];   // [589824,8]
    const float* bias = (const float*)d_in[3];   // [256]
    float* out = (float*)d_out;                  // [32,256,28,28]

    wgen_kernel<<<NWG / 256, 256>>>(wbk, se);

    dim3 grid(16, BB);          // x: 8 o-blocks * 2 row-blocks, y: batch
    dim3 block(16, ROW_TILE);   // 224 threads
    dconv_kernel<<<grid, block>>>(x, bias, out);
}

// round 6
// speedup vs baseline: 1.0006x; 1.0006x over previous
#include <cuda_runtime.h>

// ---------------------------------------------------------------------------
// DiverseRegDCConv2d: per-sample dynamically-generated 3x3 conv.
//   wgen[b,o,c,kh,kw] = sum_n se[b,n] * weight[(o*C+c)*9+kh*3+kw, n]
//   out[b,o,h,w] = sum_{c,kh,kw} wgen[b,o,c,kh,kw] * x[b,c,h+kh-1,w+kw-1] + bias[o]
// B=32, C=O=256, H=W=28, K=3, NUM=8.
// ---------------------------------------------------------------------------

#define BB   32
#define CIN  256
#define COUT 256
#define HH   28
#define WW   28
#define NUMK 8
#define WROW 2304            // CIN*9 floats per output channel
#define NWG  589824          // COUT*WROW

// Scratch for generated per-sample weights: 32 * 589824 floats = 75.5 MB
__device__ float g_wgen[(size_t)BB * NWG];

typedef unsigned long long ULL;

__device__ __forceinline__ ULL pack2(float lo, float hi) {
    ULL r; asm("mov.b64 %0, {%1, %2};" : "=l"(r) : "f"(lo), "f"(hi)); return r;
}
__device__ __forceinline__ ULL ffma2(ULL a, ULL b, ULL c) {
    ULL d; asm("fma.rn.f32x2 %0, %1, %2, %3;" : "=l"(d) : "l"(a), "l"(b), "l"(c)); return d;
}
__device__ __forceinline__ ULL fadd2(ULL a, ULL b) {
    ULL d; asm("add.rn.f32x2 %0, %1, %2;" : "=l"(d) : "l"(a), "l"(b)); return d;
}
__device__ __forceinline__ float2 unpack2(ULL v) {
    float2 f; asm("mov.b64 {%0, %1}, %2;" : "=f"(f.x), "=f"(f.y) : "l"(v)); return f;
}

// ---------------------------------------------------------------------------
// Stage 1: weight generation. Each thread owns one row j of the weight bank
// (8 floats, kept in registers) and produces wgen for all 32 samples, so the
// 18.9 MB bank is read from DRAM exactly once. Stores are fully coalesced.
// ---------------------------------------------------------------------------
__global__ void wgen_kernel(const float* __restrict__ wbank,
                            const float* __restrict__ se) {
    __shared__ float s_se[BB * NUMK];   // 256 floats
    int tid = threadIdx.x;
    s_se[tid] = se[tid];
    __syncthreads();

    unsigned j = blockIdx.x * 256u + tid;     // < 589824 (grid exact)
    const float4* w4 = (const float4*)wbank;
    float4 w0 = w4[2u * j];
    float4 w1 = w4[2u * j + 1u];

    #pragma unroll 4
    for (int b = 0; b < BB; ++b) {
        const float* s = &s_se[b * NUMK];
        float v = w0.x * s[0];
        v = fmaf(w0.y, s[1], v);
        v = fmaf(w0.z, s[2], v);
        v = fmaf(w0.w, s[3], v);
        v = fmaf(w1.x, s[4], v);
        v = fmaf(w1.y, s[5], v);
        v = fmaf(w1.z, s[6], v);
        v = fmaf(w1.w, s[7], v);
        g_wgen[(size_t)b * NWG + j] = v;
    }
}

// ---------------------------------------------------------------------------
// Stage 2: per-sample direct conv, fp32x2 packed-FMA inner loop.
// Block: 32 output channels x 14 output rows. blockDim = (16, 14) = 224 thr.
// Thread: 2 output channels (tx, tx+16) x one full 28-col row -> 14 f32x2 accs
// per channel. Channels processed in chunks of 8 through shared memory.
//
// SMEM is pre-shaped so every FFMA2 operand is a single aligned LDS.64:
//   - weights duplicated as (w,w) float2, stride 73 pairs  -> conflict-free
//   - input rows stored twice: natural (cols -1..30 at entries 0..31) and
//     shifted by one (col s at entry s), both stride-34 padded. Even-entry
//     pairs of the two copies give tap0/tap2 and tap1 operands directly.
// ---------------------------------------------------------------------------
#define CC_CHUNK 8
#define O_TILE   32
#define ROW_TILE 14
#define WP_STRIDE 73         // float2 pairs per o-channel row (72 + 1 pad)
#define XR_STRIDE 34         // floats per input row (32 + 2 pad)

#define W_PAIRS   (O_TILE * WP_STRIDE)             // 2336 float2
#define X_FLOATS  (CC_CHUNK * 16 * XR_STRIDE)      // 4352 floats
#define SMEM_BYTES (W_PAIRS * 8 + 2 * X_FLOATS * 4)  // 18688 + 34816 = 53504

__global__ __launch_bounds__(224, 2)
void dconv_kernel(const float* __restrict__ x,
                  const float* __restrict__ bias,
                  float* __restrict__ out) {
    extern __shared__ float smem[];
    float2* wsm  = (float2*)smem;                  // [32][73] duplicated pairs
    float*  xsm  = smem + W_PAIRS * 2;             // [8][16][34], entry s = col s-1
    float*  xsm2 = xsm + X_FLOATS;                 // [8][16][34], entry s = col s

    const int tx  = threadIdx.x;          // 0..15 : o-lane
    const int ty  = threadIdx.y;          // 0..13 : row
    const int tid = tx + ty * 16;         // 0..223

    const int b       = blockIdx.y;
    const int ob      = blockIdx.x >> 1;  // 0..7
    const int rb      = blockIdx.x & 1;   // 0..1
    const int oBase   = ob * O_TILE;
    const int rowBase = rb * ROW_TILE;

    ULL acc[2][14];
    #pragma unroll
    for (int oo = 0; oo < 2; ++oo)
        #pragma unroll
        for (int j = 0; j < 14; ++j) acc[oo][j] = 0ull;

    const float* wg = g_wgen + ((size_t)b * COUT + oBase) * WROW; // [32][2304]
    const float* xb = x + (size_t)b * CIN * (HH * WW);

    for (int c0 = 0; c0 < CIN; c0 += CC_CHUNK) {
        __syncthreads();   // previous chunk's smem reads done before refill

        // --- weight tile: 32 o x 72 floats, stored duplicated as (w,w) pairs
        for (int i = tid; i < O_TILE * 72; i += 224) {
            int o = i / 72;
            int r = i - o * 72;
            float v = wg[(size_t)o * WROW + c0 * 9 + r];
            wsm[o * WP_STRIDE + r] = make_float2(v, v);
        }
        // --- input tile: 8cc x 16 rows x 32 cols, zero-padded halo,
        //     written to both the natural and the shifted copy.
        for (int i = tid; i < CC_CHUNK * 16 * 32; i += 224) {
            int cc  = i >> 9;
            int rem = i & 511;
            int row = rem >> 5;
            int s   = rem & 31;
            int ih  = rowBase - 1 + row;
            int iw  = s - 1;
            float v = 0.0f;
            if ((unsigned)ih < (unsigned)HH && (unsigned)iw < (unsigned)WW)
                v = xb[((c0 + cc) * HH + ih) * WW + iw];
            int base = (cc * 16 + row) * XR_STRIDE;
            xsm[base + s] = v;
            if (s >= 1) xsm2[base + s - 1] = v;
        }
        __syncthreads();

        #pragma unroll 2
        for (int cc = 0; cc < CC_CHUNK; ++cc) {
            const ULL* wp0 = (const ULL*)(wsm + tx * WP_STRIDE + cc * 9);
            const ULL* wp1 = (const ULL*)(wsm + (tx + 16) * WP_STRIDE + cc * 9);
            #pragma unroll
            for (int r = 0; r < 3; ++r) {
                ULL w00 = wp0[r * 3 + 0];
                ULL w01 = wp0[r * 3 + 1];
                ULL w02 = wp0[r * 3 + 2];
                ULL w10 = wp1[r * 3 + 0];
                ULL w11 = wp1[r * 3 + 1];
                ULL w12 = wp1[r * 3 + 2];
                const ULL* Ep = (const ULL*)(xsm  + (cc * 16 + ty + r) * XR_STRIDE);
                const ULL* Dp = (const ULL*)(xsm2 + (cc * 16 + ty + r) * XR_STRIDE);
                ULL aE0 = Ep[0];                     // cols (2j-1, 2j) at j=0
                #pragma unroll
                for (int j = 0; j < 14; ++j) {
                    ULL aE1 = Ep[j + 1];             // cols (2j+1, 2j+2)
                    ULL aD  = Dp[j];                 // cols (2j,   2j+1)
                    acc[0][j] = ffma2(w00, aE0, acc[0][j]);
                    acc[0][j] = ffma2(w01, aD,  acc[0][j]);
                    acc[0][j] = ffma2(w02, aE1, acc[0][j]);
                    acc[1][j] = ffma2(w10, aE0, acc[1][j]);
                    acc[1][j] = ffma2(w11, aD,  acc[1][j]);
                    acc[1][j] = ffma2(w12, aE1, acc[1][j]);
                    aE0 = aE1;
                }
            }
        }
    }

    // --- epilogue: add bias, store one full row per (thread, channel)
    const int h = rowBase + ty;
    #pragma unroll
    for (int oo = 0; oo < 2; ++oo) {
        int o = oBase + tx + 16 * oo;
        float bv = bias[o];
        ULL bv2 = pack2(bv, bv);
        float2* op = (float2*)(out + (((size_t)b * COUT + o) * HH + h) * WW);
        #pragma unroll
        for (int j = 0; j < 14; ++j) {
            op[j] = unpack2(fadd2(acc[oo][j], bv2));
        }
    }
}

// ---------------------------------------------------------------------------
// Harness entry. Inputs (metadata order): inputs, inputs_se, weight, bias.
// ---------------------------------------------------------------------------
extern "C" void kernel_launch(void* const* d_in, const int* in_sizes, int n_in,
                              void* d_out, int out_size) {
    const float* x    = (const float*)d_in[0];   // [32,256,28,28]
    const float* se   = (const float*)d_in[1];   // [32,8]
    const float* wbk  = (const float*)d_in[2];   // [589824,8]
    const float* bias = (const float*)d_in[3];   // [256]
    float* out = (float*)d_out;                  // [32,256,28,28]

    static bool attr_done = false;
    if (!attr_done) {
        cudaFuncSetAttribute(dconv_kernel,
                             cudaFuncAttributeMaxDynamicSharedMemorySize,
                             SMEM_BYTES);
        attr_done = true;
    }

    wgen_kernel<<<NWG / 256, 256>>>(wbk, se);

    dim3 grid(16, BB);          // x: 8 o-blocks * 2 row-blocks, y: batch
    dim3 block(16, ROW_TILE);   // 224 threads
    dconv_kernel<<<grid, block, SMEM_BYTES>>>(x, bias, out);
}

// round 7
// speedup vs baseline: 1.1610x; 1.1603x over previous
#include <cuda_runtime.h>
#include <cstdint>

// ---------------------------------------------------------------------------
// DiverseRegDCConv2d: per-sample dynamically-generated 3x3 conv.
//   wgen[b,o,c,kh,kw] = sum_n se[b,n] * weight[(o*C+c)*9+kh*3+kw, n]
//   out[b,o,h,w] = sum_{c,kh,kw} wgen[b,o,c,kh,kw] * x[b,c,h+kh-1,w+kw-1] + bias[o]
// B=32, C=O=256, H=W=28, K=3, NUM=8.
// ---------------------------------------------------------------------------

#define BB   32
#define CIN  256
#define COUT 256
#define HH   28
#define WW   28
#define NUMK 8
#define WROW 2304            // CIN*9 floats per output channel
#define NWG  589824          // COUT*WROW

// Scratch for generated per-sample weights: 32 * 589824 floats = 75.5 MB
__device__ float g_wgen[(size_t)BB * NWG];

typedef unsigned long long ULL;

__device__ __forceinline__ ULL pack2(float lo, float hi) {
    ULL r; asm("mov.b64 %0, {%1, %2};" : "=l"(r) : "f"(lo), "f"(hi)); return r;
}
__device__ __forceinline__ ULL ffma2(ULL a, ULL b, ULL c) {
    ULL d; asm("fma.rn.f32x2 %0, %1, %2, %3;" : "=l"(d) : "l"(a), "l"(b), "l"(c)); return d;
}
__device__ __forceinline__ ULL fadd2(ULL a, ULL b) {
    ULL d; asm("add.rn.f32x2 %0, %1, %2;" : "=l"(d) : "l"(a), "l"(b)); return d;
}
__device__ __forceinline__ float2 unpack2(ULL v) {
    float2 f; asm("mov.b64 {%0, %1}, %2;" : "=f"(f.x), "=f"(f.y) : "l"(v)); return f;
}
__device__ __forceinline__ void cp16(uint32_t dst, const void* src) {
    asm volatile("cp.async.ca.shared.global [%0], [%1], 16;\n"
                 :: "r"(dst), "l"(src) : "memory");
}
#define CP_COMMIT() asm volatile("cp.async.commit_group;\n" ::: "memory")
#define CP_WAIT0()  asm volatile("cp.async.wait_group 0;\n" ::: "memory")

// ---------------------------------------------------------------------------
// Stage 1: weight generation (reads 18.9MB bank once, writes 75.5MB wgen)
// ---------------------------------------------------------------------------
__global__ void wgen_kernel(const float* __restrict__ wbank,
                            const float* __restrict__ se) {
    __shared__ float s_se[BB * NUMK];
    int tid = threadIdx.x;
    s_se[tid] = se[tid];
    __syncthreads();

    unsigned j = blockIdx.x * 256u + tid;
    const float4* w4 = (const float4*)wbank;
    float4 w0 = w4[2u * j];
    float4 w1 = w4[2u * j + 1u];

    #pragma unroll 4
    for (int b = 0; b < BB; ++b) {
        const float* s = &s_se[b * NUMK];
        float v = w0.x * s[0];
        v = fmaf(w0.y, s[1], v);
        v = fmaf(w0.z, s[2], v);
        v = fmaf(w0.w, s[3], v);
        v = fmaf(w1.x, s[4], v);
        v = fmaf(w1.y, s[5], v);
        v = fmaf(w1.z, s[6], v);
        v = fmaf(w1.w, s[7], v);
        g_wgen[(size_t)b * NWG + j] = v;
    }
}

// ---------------------------------------------------------------------------
// Stage 2: direct conv, fp32x2 FMAs, cp.async double-buffered smem.
// Block (16,14) = 224 thr: 32 o-channels x 7 output rows per block.
// Thread: 1 o-channel x 1 row x 28 cols = 14 f32x2 accumulators.
// __launch_bounds__(224,4) -> 4 blocks/SM = 28 warps, grid = 1024 blocks.
// ---------------------------------------------------------------------------
#define CC   8               // channels per chunk
#define OT   32              // o-channels per block
#define RT   7               // output rows per block
#define NR   9               // input rows staged (RT + 2 halo)
#define WS_  76              // floats per o weight row (72 + pad, 16B mult)
#define XS_  36              // floats per input row (28 + halo/pad, 16B mult)
#define WBUF (OT * WS_)      // 2432 floats per weight buffer
#define XBUF (CC * NR * XS_) // 2592 floats per input buffer
#define SMEM_BYTES ((2 * WBUF + 2 * XBUF) * 4)   // 40192 B

__global__ __launch_bounds__(224, 4)
void dconv_kernel(const float* __restrict__ x,
                  const float* __restrict__ bias,
                  float* __restrict__ out) {
    extern __shared__ float smem[];
    float* ws = smem;                  // [2][32][76] raw weights
    float* xs = smem + 2 * WBUF;       // [2][8][9][36] input rows (col c @ entry c)

    const int tx  = threadIdx.x;       // 0..15
    const int ty  = threadIdx.y;       // 0..13
    const int tid = ty * 16 + tx;
    const int row = ty % 7;            // output row within block
    const int oh  = ty / 7;            // o half
    const int olocal = oh * 16 + tx;   // 0..31

    const int b       = blockIdx.y;
    const int ob      = blockIdx.x >> 2;   // 0..7
    const int rb      = blockIdx.x & 3;    // 0..3
    const int oBase   = ob * OT;
    const int rowBase = rb * RT;

    const float* wg = g_wgen + ((size_t)b * COUT + oBase) * WROW;
    const float* xb = x + (size_t)b * CIN * (HH * WW);

    const uint32_t ws_u = (uint32_t)__cvta_generic_to_shared(ws);
    const uint32_t xs_u = (uint32_t)__cvta_generic_to_shared(xs);

    // Zero both input buffers once: pad columns (28..35) and halo/invalid rows
    // stay zero forever; cp.async only ever writes the 28 valid columns.
    {
        float4* xz = (float4*)xs;
        for (int i = tid; i < (2 * XBUF) / 4; i += 224)
            xz[i] = make_float4(0.f, 0.f, 0.f, 0.f);
    }
    __syncthreads();   // zeros visible before any cp.async fill of same region

    ULL acc[14];
    #pragma unroll
    for (int j = 0; j < 14; ++j) acc[j] = 0ull;

    // ---- prologue: async-fill chunk 0 into buffer 0
    {
        for (int i = tid; i < OT * 18; i += 224) {      // 32 o x 18 16B chunks
            int o = i / 18, ch = i % 18;
            cp16(ws_u + (o * WS_ + ch * 4) * 4,
                 wg + (size_t)o * WROW + ch * 4);
        }
        for (int i = tid; i < CC * NR * 7; i += 224) {  // 8 cc x 9 rows x 7 chunks
            int cc = i / 63, rem = i % 63, rw = rem / 7, ch = rem % 7;
            int ih = rowBase - 1 + rw;
            if ((unsigned)ih < (unsigned)HH)
                cp16(xs_u + ((cc * NR + rw) * XS_ + ch * 4) * 4,
                     xb + ((size_t)cc * HH + ih) * WW + ch * 4);
        }
        CP_COMMIT();
    }

    for (int k = 0; k < CIN / CC; ++k) {
        CP_WAIT0();        // chunk k's copies done (had full compute k-1 to land)
        __syncthreads();   // data visible to all; buf (k+1)&1 free to overwrite

        if (k < CIN / CC - 1) {
            const int c0 = (k + 1) * CC;
            const uint32_t wd = ws_u + (((k + 1) & 1) * WBUF) * 4;
            const uint32_t xd = xs_u + (((k + 1) & 1) * XBUF) * 4;
            for (int i = tid; i < OT * 18; i += 224) {
                int o = i / 18, ch = i % 18;
                cp16(wd + (o * WS_ + ch * 4) * 4,
                     wg + (size_t)o * WROW + c0 * 9 + ch * 4);
            }
            for (int i = tid; i < CC * NR * 7; i += 224) {
                int cc = i / 63, rem = i % 63, rw = rem / 7, ch = rem % 7;
                int ih = rowBase - 1 + rw;
                if ((unsigned)ih < (unsigned)HH)
                    cp16(xd + ((cc * NR + rw) * XS_ + ch * 4) * 4,
                         xb + ((size_t)(c0 + cc) * HH + ih) * WW + ch * 4);
            }
            CP_COMMIT();
        }

        const float* wsb = ws + (k & 1) * WBUF + olocal * WS_;
        const float* xsb = xs + (k & 1) * XBUF;

        for (int cc = 0; cc < CC; ++cc) {
            #pragma unroll
            for (int r = 0; r < 3; ++r) {
                const float* wp = wsb + cc * 9 + r * 3;
                float wv0 = wp[0], wv1 = wp[1], wv2 = wp[2];
                ULL w0 = pack2(wv0, wv0);
                ULL w1 = pack2(wv1, wv1);
                ULL w2 = pack2(wv2, wv2);
                const float2* Ap = (const float2*)(xsb + (cc * NR + row + r) * XS_);
                float2 a0 = Ap[0];                 // cols (0,1)
                ULL Acur = pack2(a0.x, a0.y);
                ULL O    = pack2(0.0f, a0.x);      // cols (-1,0); col -1 == 0 (pad)
                #pragma unroll
                for (int j = 0; j < 14; ++j) {
                    float2 a1 = Ap[j + 1];         // cols (2j+2, 2j+3); j=13 -> zeros
                    ULL Anext = pack2(a1.x, a1.y);
                    ULL On    = pack2(a0.y, a1.x); // cols (2j+1, 2j+2)
                    ULL t = ffma2(w0, O,    acc[j]);   // taps (2j-1, 2j)
                    t     = ffma2(w1, Acur, t);        // taps (2j,   2j+1)
                    acc[j] = ffma2(w2, On,  t);        // taps (2j+1, 2j+2)
                    a0 = a1; Acur = Anext; O = On;
                }
            }
        }
    }

    // ---- epilogue
    const int o = oBase + olocal;
    const int h = rowBase + row;
    float bv = bias[o];
    ULL bv2 = pack2(bv, bv);
    float2* op = (float2*)(out + (((size_t)b * COUT + o) * HH + h) * WW);
    #pragma unroll
    for (int j = 0; j < 14; ++j)
        op[j] = unpack2(fadd2(acc[j], bv2));
}

// ---------------------------------------------------------------------------
// Harness entry. Inputs (metadata order): inputs, inputs_se, weight, bias.
// ---------------------------------------------------------------------------
extern "C" void kernel_launch(void* const* d_in, const int* in_sizes, int n_in,
                              void* d_out, int out_size) {
    const float* x    = (const float*)d_in[0];   // [32,256,28,28]
    const float* se   = (const float*)d_in[1];   // [32,8]
    const float* wbk  = (const float*)d_in[2];   // [589824,8]
    const float* bias = (const float*)d_in[3];   // [256]
    float* out = (float*)d_out;                  // [32,256,28,28]

    wgen_kernel<<<NWG / 256, 256>>>(wbk, se);

    dim3 grid(32, BB);          // x: 8 o-blocks * 4 row-blocks, y: batch
    dim3 block(16, 14);         // 224 threads
    dconv_kernel<<<grid, block, SMEM_BYTES>>>(x, bias, out);
}

// round 8
// speedup vs baseline: 1.2137x; 1.0454x over previous
#include <cuda_runtime.h>
#include <cstdint>

// ---------------------------------------------------------------------------
// DiverseRegDCConv2d: per-sample dynamically-generated 3x3 conv.
//   wgen[b,o,c,kh,kw] = sum_n se[b,n] * weight[(o*C+c)*9+kh*3+kw, n]
//   out[b,o,h,w] = sum_{c,kh,kw} wgen[b,o,c,kh,kw] * x[b,c,h+kh-1,w+kw-1] + bias[o]
// B=32, C=O=256, H=W=28, K=3, NUM=8.
// ---------------------------------------------------------------------------

#define BB   32
#define CIN  256
#define COUT 256
#define HH   28
#define WW   28
#define NUMK 8
#define WROW 2304            // CIN*9 floats per output channel
#define NWG  589824          // COUT*WROW

__device__ float g_wgen[(size_t)BB * NWG];   // 75.5 MB generated weights

typedef unsigned long long ULL;

__device__ __forceinline__ ULL pack2(float lo, float hi) {
    ULL r; asm("mov.b64 %0, {%1, %2};" : "=l"(r) : "f"(lo), "f"(hi)); return r;
}
__device__ __forceinline__ ULL ffma2(ULL a, ULL b, ULL c) {
    ULL d; asm("fma.rn.f32x2 %0, %1, %2, %3;" : "=l"(d) : "l"(a), "l"(b), "l"(c)); return d;
}
__device__ __forceinline__ ULL fadd2(ULL a, ULL b) {
    ULL d; asm("add.rn.f32x2 %0, %1, %2;" : "=l"(d) : "l"(a), "l"(b)); return d;
}
__device__ __forceinline__ float2 unpack2(ULL v) {
    float2 f; asm("mov.b64 {%0, %1}, %2;" : "=f"(f.x), "=f"(f.y) : "l"(v)); return f;
}
__device__ __forceinline__ void cp16(uint32_t dst, const void* src) {
    asm volatile("cp.async.ca.shared.global [%0], [%1], 16;\n"
                 :: "r"(dst), "l"(src) : "memory");
}
__device__ __forceinline__ void cp4(uint32_t dst, const void* src) {
    asm volatile("cp.async.ca.shared.global [%0], [%1], 4;\n"
                 :: "r"(dst), "l"(src) : "memory");
}
#define CP_COMMIT() asm volatile("cp.async.commit_group;\n" ::: "memory")
#define CP_WAIT0()  asm volatile("cp.async.wait_group 0;\n" ::: "memory")

// ---------------------------------------------------------------------------
// Stage 1: weight generation (reads 18.9MB bank once, writes 75.5MB wgen)
// ---------------------------------------------------------------------------
__global__ void wgen_kernel(const float* __restrict__ wbank,
                            const float* __restrict__ se) {
    __shared__ float s_se[BB * NUMK];
    int tid = threadIdx.x;
    s_se[tid] = se[tid];
    __syncthreads();

    unsigned j = blockIdx.x * 256u + tid;
    const float4* w4 = (const float4*)wbank;
    float4 w0 = w4[2u * j];
    float4 w1 = w4[2u * j + 1u];

    #pragma unroll 4
    for (int b = 0; b < BB; ++b) {
        const float* s = &s_se[b * NUMK];
        float v = w0.x * s[0];
        v = fmaf(w0.y, s[1], v);
        v = fmaf(w0.z, s[2], v);
        v = fmaf(w0.w, s[3], v);
        v = fmaf(w1.x, s[4], v);
        v = fmaf(w1.y, s[5], v);
        v = fmaf(w1.z, s[6], v);
        v = fmaf(w1.w, s[7], v);
        g_wgen[(size_t)b * NWG + j] = v;
    }
}

// ---------------------------------------------------------------------------
// Stage 2: direct conv. Block (16,14)=224 thr: 32 o-channels x 7 rows.
// Thread: 1 o-channel x 1 row x 28 cols = 14 f32x2 accumulators.
// Input rows staged in SMEM in TWO alignments so every FFMA2 operand is one
// aligned LDS.64:
//   copy A: entry c  = col c      -> Aq[j] = cols(2j,   2j+1)  (tap kw=1)
//   copy B: entry c+1= col c      -> Bq[j] = cols(2j-1, 2j)    (tap kw=0)
//                                    Bq[j+1]= cols(2j+1, 2j+2) (tap kw=2)
// ---------------------------------------------------------------------------
#define CC   8               // channels per chunk
#define OT   32              // o-channels per block
#define RT   7               // output rows per block
#define NR   9               // input rows staged (RT + 2 halo)
#define WS_  76              // floats per o weight row (72 + pad, 16B mult)
#define XROW 64              // floats per staged row: A[32] | B[32]
#define WBUF (OT * WS_)      // 2432 floats per weight buffer
#define XBUF (CC * NR * XROW)// 4608 floats per input buffer
#define SMEM_BYTES ((2 * WBUF + 2 * XBUF) * 4)   // 19456 + 36864 = 56320 B

__global__ __launch_bounds__(224, 4)
void dconv_kernel(const float* __restrict__ x,
                  const float* __restrict__ bias,
                  float* __restrict__ out) {
    extern __shared__ float smem[];
    float* ws = smem;                  // [2][32][76] raw weights
    float* xs = smem + 2 * WBUF;       // [2][8][9][64] dual-aligned input rows

    const int tx  = threadIdx.x;       // 0..15
    const int ty  = threadIdx.y;       // 0..13
    const int tid = ty * 16 + tx;
    const int row = ty % 7;            // output row within block
    const int oh  = ty / 7;            // o half
    const int olocal = oh * 16 + tx;   // 0..31

    const int b       = blockIdx.y;
    const int ob      = blockIdx.x >> 2;   // 0..7
    const int rb      = blockIdx.x & 3;    // 0..3
    const int oBase   = ob * OT;
    const int rowBase = rb * RT;

    const float* wg = g_wgen + ((size_t)b * COUT + oBase) * WROW;
    const float* xb = x + (size_t)b * CIN * (HH * WW);

    const uint32_t ws_u = (uint32_t)__cvta_generic_to_shared(ws);
    const uint32_t xs_u = (uint32_t)__cvta_generic_to_shared(xs);

    // Zero both input buffers once: halo/pad entries stay zero forever.
    {
        float4* xz = (float4*)xs;
        for (int i = tid; i < (2 * XBUF) / 4; i += 224)
            xz[i] = make_float4(0.f, 0.f, 0.f, 0.f);
    }
    __syncthreads();

    ULL acc[14];
    #pragma unroll
    for (int j = 0; j < 14; ++j) acc[j] = 0ull;

    // ---- prologue: async-fill chunk 0 into buffer 0
    {
        for (int i = tid; i < OT * 18; i += 224) {          // weights, 16B
            int o = i / 18, ch = i % 18;
            cp16(ws_u + (o * WS_ + ch * 4) * 4,
                 wg + (size_t)o * WROW + ch * 4);
        }
        for (int i = tid; i < CC * NR * 7; i += 224) {      // copy A, 16B
            int cc = i / 63, rem = i % 63, rw = rem / 7, ch = rem % 7;
            int ih = rowBase - 1 + rw;
            if ((unsigned)ih < (unsigned)HH)
                cp16(xs_u + ((cc * NR + rw) * XROW + ch * 4) * 4,
                     xb + ((size_t)cc * HH + ih) * WW + ch * 4);
        }
        for (int i = tid; i < CC * NR * 28; i += 224) {     // copy B, 4B shifted
            int cc = i / 252, rem = i % 252, rw = rem / 28, c = rem % 28;
            int ih = rowBase - 1 + rw;
            if ((unsigned)ih < (unsigned)HH)
                cp4(xs_u + ((cc * NR + rw) * XROW + 32 + c + 1) * 4,
                    xb + ((size_t)cc * HH + ih) * WW + c);
        }
        CP_COMMIT();
    }

    for (int k = 0; k < CIN / CC; ++k) {
        CP_WAIT0();
        __syncthreads();

        if (k < CIN / CC - 1) {
            const int c0 = (k + 1) * CC;
            const uint32_t wd = ws_u + (((k + 1) & 1) * WBUF) * 4;
            const uint32_t xd = xs_u + (((k + 1) & 1) * XBUF) * 4;
            for (int i = tid; i < OT * 18; i += 224) {
                int o = i / 18, ch = i % 18;
                cp16(wd + (o * WS_ + ch * 4) * 4,
                     wg + (size_t)o * WROW + c0 * 9 + ch * 4);
            }
            for (int i = tid; i < CC * NR * 7; i += 224) {
                int cc = i / 63, rem = i % 63, rw = rem / 7, ch = rem % 7;
                int ih = rowBase - 1 + rw;
                if ((unsigned)ih < (unsigned)HH)
                    cp16(xd + ((cc * NR + rw) * XROW + ch * 4) * 4,
                         xb + ((size_t)(c0 + cc) * HH + ih) * WW + ch * 4);
            }
            for (int i = tid; i < CC * NR * 28; i += 224) {
                int cc = i / 252, rem = i % 252, rw = rem / 28, c = rem % 28;
                int ih = rowBase - 1 + rw;
                if ((unsigned)ih < (unsigned)HH)
                    cp4(xd + ((cc * NR + rw) * XROW + 32 + c + 1) * 4,
                        xb + ((size_t)(c0 + cc) * HH + ih) * WW + c);
            }
            CP_COMMIT();
        }

        const float* wsb = ws + (k & 1) * WBUF + olocal * WS_;
        const float* xsb = xs + (k & 1) * XBUF;

        for (int cc = 0; cc < CC; ++cc) {
            #pragma unroll
            for (int r = 0; r < 3; ++r) {
                const float* wp = wsb + cc * 9 + r * 3;
                float wv0 = wp[0], wv1 = wp[1], wv2 = wp[2];
                ULL w0 = pack2(wv0, wv0);
                ULL w1 = pack2(wv1, wv1);
                ULL w2 = pack2(wv2, wv2);
                const float* xr = xsb + (cc * NR + row + r) * XROW;
                const ULL* Aq = (const ULL*)xr;          // cols (2j,   2j+1)
                const ULL* Bq = (const ULL*)(xr + 32);   // cols (2j-1, 2j)
                ULL b0 = Bq[0];
                #pragma unroll
                for (int j = 0; j < 14; ++j) {
                    ULL aj = Aq[j];
                    ULL b1 = Bq[j + 1];
                    ULL t  = ffma2(w0, b0, acc[j]);   // taps (2j-1, 2j)
                    t      = ffma2(w1, aj, t);        // taps (2j,   2j+1)
                    acc[j] = ffma2(w2, b1, t);        // taps (2j+1, 2j+2)
                    b0 = b1;
                }
            }
        }
    }

    // ---- epilogue
    const int o = oBase + olocal;
    const int h = rowBase + row;
    float bv = bias[o];
    ULL bv2 = pack2(bv, bv);
    float2* op = (float2*)(out + (((size_t)b * COUT + o) * HH + h) * WW);
    #pragma unroll
    for (int j = 0; j < 14; ++j)
        op[j] = unpack2(fadd2(acc[j], bv2));
}

// ---------------------------------------------------------------------------
// Harness entry. Inputs (metadata order): inputs, inputs_se, weight, bias.
// ---------------------------------------------------------------------------
extern "C" void kernel_launch(void* const* d_in, const int* in_sizes, int n_in,
                              void* d_out, int out_size) {
    const float* x    = (const float*)d_in[0];   // [32,256,28,28]
    const float* se   = (const float*)d_in[1];   // [32,8]
    const float* wbk  = (const float*)d_in[2];   // [589824,8]
    const float* bias = (const float*)d_in[3];   // [256]
    float* out = (float*)d_out;                  // [32,256,28,28]

    // Host-side attributes (idempotent, not stream ops; capture-safe).
    cudaFuncSetAttribute(dconv_kernel,
                         cudaFuncAttributeMaxDynamicSharedMemorySize,
                         SMEM_BYTES);
    cudaFuncSetAttribute(dconv_kernel,
                         cudaFuncAttributePreferredSharedMemoryCarveout, 100);

    wgen_kernel<<<NWG / 256, 256>>>(wbk, se);

    dim3 grid(32, BB);          // x: 8 o-blocks * 4 row-blocks, y: batch
    dim3 block(16, 14);         // 224 threads
    dconv_kernel<<<grid, block, SMEM_BYTES>>>(x, bias, out);
}